// round 4
// baseline (speedup 1.0000x reference)
#include <cuda_runtime.h>
#include <cstdint>

// ---------------------------------------------------------------------------
// Round 4:
//   pool: 32-slot buckets (no prefix scan) -> fill -> gather
//   up:   mma.sync bf16 m16n8k16, 3-chain split (ah*bh + ah*bl + al*bh),
//         k-sorted 64-pair tiles, B cached in registers, v2-RED scatter.
//   Launch order puts up_mma at position 4 so ncu finally profiles it.
// ---------------------------------------------------------------------------

__device__ float4 g_pooled4[1000000 * 8];   // pooled rows (pre-divided)
__device__ int    g_cursor [1000000];
__device__ int    g_csr    [32000000];      // 32-slot buckets per pooled row

static __device__ __forceinline__ void red_add_v2(float* dst, float a, float b) {
    asm volatile("red.global.add.v2.f32 [%0], {%1,%2};"
                 :: "l"(dst), "f"(a), "f"(b) : "memory");
}
static __device__ __forceinline__ uint32_t bf2(float hi, float lo) {
    uint32_t r;
    asm("cvt.rn.bf16x2.f32 %0, %1, %2;" : "=r"(r) : "f"(hi), "f"(lo));
    return r;
}
// split (v0=low channel, v1=high channel) -> hi/lo bf16x2 pair
static __device__ __forceinline__ void split2(float v0, float v1,
                                              uint32_t& h, uint32_t& l) {
    h = bf2(v1, v0);
    float f0 = __uint_as_float(h << 16);
    float f1 = __uint_as_float(h & 0xFFFF0000u);
    l = bf2(v1 - f1, v0 - f0);
}
static __device__ __forceinline__ void mma_bf16(float c[4],
        uint32_t a0, uint32_t a1, uint32_t a2, uint32_t a3,
        uint32_t b0, uint32_t b1) {
    asm volatile(
        "mma.sync.aligned.m16n8k16.row.col.f32.bf16.bf16.f32 "
        "{%0,%1,%2,%3}, {%4,%5,%6,%7}, {%8,%9}, {%0,%1,%2,%3};"
        : "+f"(c[0]), "+f"(c[1]), "+f"(c[2]), "+f"(c[3])
        : "r"(a0), "r"(a1), "r"(a2), "r"(a3), "r"(b0), "r"(b1));
}

// ---- launch 1: zero bucket cursors + out = feat - bias (fused) --------------
__global__ void prep_kernel(const float4* __restrict__ feat4,
                            const float4* __restrict__ bias4,
                            float4* __restrict__ out4, int M, int n8, int gz) {
    if ((int)blockIdx.x < gz) {
        int i = blockIdx.x * 256 + threadIdx.x;
        if (i < M) g_cursor[i] = 0;
        return;
    }
    int t = (blockIdx.x - gz) * 256 + threadIdx.x;
    if (t >= n8) return;
    float4 v = feat4[t];
    float4 b = __ldg(bias4 + (t & 7));
    out4[t] = make_float4(v.x - b.x, v.y - b.y, v.z - b.z, v.w - b.w);
}

// ---- launch 2: scatter pair list into buckets --------------------------------
__global__ void fill_kernel(const int* __restrict__ pin,
                            const int* __restrict__ pout, int P) {
    int p = blockIdx.x * 256 + threadIdx.x;
    if (p < P) {
        int o = __ldg(pout + p);
        int s = atomicAdd(&g_cursor[o], 1);
        g_csr[(size_t)o * 32 + s] = __ldg(pin + p);
    }
}

// ---- launch 3: pooled[m] = (1/cnt) * sum of bucket rows ----------------------
__global__ void pool_gather_kernel(const float4* __restrict__ feat4,
                                   const int* __restrict__ counts, int M) {
    int t = blockIdx.x * 256 + threadIdx.x;
    if (t >= M * 8) return;
    int m = t >> 3, cg = t & 7;
    int cnt = counts[m];
    const int* row = g_csr + (size_t)m * 32;
    float4 acc = make_float4(0.f, 0.f, 0.f, 0.f);
    for (int e = 0; e < cnt; e++) {
        int idx = __ldg(row + e);
        float4 v = __ldg(&feat4[(size_t)idx * 8 + cg]);
        acc.x += v.x; acc.y += v.y; acc.z += v.z; acc.w += v.w;
    }
    float inv = 1.0f / (float)cnt;
    g_pooled4[(size_t)m * 8 + cg] =
        make_float4(acc.x * inv, acc.y * inv, acc.z * inv, acc.w * inv);
}

// ---- launch 4: up pass, split-bf16 mma ---------------------------------------
// Tile: 4 warps x 16 pairs. D[16x32] += A(16x32) x (-W[k])(32x32)
// SMEM word-stride 20: A/B fragment LDS are 32-bank conflict-free.
__global__ void __launch_bounds__(128)
up_mma_kernel(const float* __restrict__ weight,
              const int* __restrict__ uin,
              const int* __restrict__ uout,
              const int* __restrict__ uk,
              float* __restrict__ out, int U, int ntiles) {
    __shared__ __align__(16) uint32_t sAh[4][16 * 20];
    __shared__ __align__(16) uint32_t sAl[4][16 * 20];
    __shared__ __align__(16) uint32_t sBh[32 * 20];
    __shared__ __align__(16) uint32_t sBl[32 * 20];
    __shared__ int s_in[64], s_out[64], s_k[64];
    __shared__ int s_kmin, s_kmax;

    int tid = threadIdx.x, w = tid >> 5, lane = tid & 31;
    int ar = lane >> 2;   // fragment row base (0..7)
    int ac = lane & 3;    // fragment col-pair base (0..3)

    int chunk = (ntiles + gridDim.x - 1) / gridDim.x;
    int t0 = blockIdx.x * chunk;
    int t1 = min(t0 + chunk, ntiles);
    int lastk = -1;
    uint32_t bh[4][2][2], bl[4][2][2];   // [nt][kt][reg]

    for (int t = t0; t < t1; t++) {
        int base = t * 64;
        __syncthreads();
        if (tid == 0) { s_kmin = 1 << 30; s_kmax = -1; }
        if (tid < 64) {
            int p = base + tid;
            int kk = (p < U) ? __ldg(uk + p) : -1;
            s_k[tid] = kk;
            s_in[tid] = (p < U) ? __ldg(uin + p) : 0;
            s_out[tid] = (p < U) ? __ldg(uout + p) : 0;
        }
        __syncthreads();
        if (tid < 64 && s_k[tid] >= 0) {
            atomicMin(&s_kmin, s_k[tid]);
            atomicMax(&s_kmax, s_k[tid]);
        }
        __syncthreads();
        int kmin = s_kmin, kmax = s_kmax;

        float c[4][4];
        #pragma unroll
        for (int i = 0; i < 4; i++)
            #pragma unroll
            for (int j = 0; j < 4; j++) c[i][j] = 0.f;

        for (int k = kmin; k <= kmax; k++) {
            bool newk = (k != lastk);   // block-uniform
            if (newk) {
                __syncthreads();
                // B[j-pair][n] = -W[k][2j..2j+1][n], split bf16
                #pragma unroll
                for (int it = 0; it < 4; it++) {
                    int idx = it * 128 + tid;     // 512 slots
                    int j = idx >> 5, n = idx & 31;
                    const float* wp = weight + (size_t)k * 1024 + (size_t)(2 * j) * 32 + n;
                    float w0 = -__ldg(wp);
                    float w1 = -__ldg(wp + 32);
                    uint32_t h, l;
                    split2(w0, w1, h, l);
                    sBh[n * 20 + j] = h;
                    sBl[n * 20 + j] = l;
                }
                __syncthreads();
            }
            // stage A (per warp; rows whose k != current get zeros)
            __syncwarp();
            #pragma unroll
            for (int i = 0; i < 4; i++) {
                int idx = i * 32 + lane;
                int row = idx >> 3, cg = idx & 7;   // float4 = channels 4cg..4cg+3
                bool act = (s_k[w * 16 + row] == k);
                float4 v = act ? __ldg(&g_pooled4[(size_t)s_in[w * 16 + row] * 8 + cg])
                               : make_float4(0.f, 0.f, 0.f, 0.f);
                uint32_t h0, l0, h1, l1;
                split2(v.x, v.y, h0, l0);
                split2(v.z, v.w, h1, l1);
                int a = row * 20 + 2 * cg;
                sAh[w][a] = h0; sAh[w][a + 1] = h1;
                sAl[w][a] = l0; sAl[w][a + 1] = l1;
            }
            __syncwarp();
            if (newk) {   // refill B register cache
                #pragma unroll
                for (int nt = 0; nt < 4; nt++) {
                    int n = (ar + 8 * nt) * 20;
                    #pragma unroll
                    for (int kt = 0; kt < 2; kt++) {
                        bh[nt][kt][0] = sBh[n + ac + 8 * kt];
                        bh[nt][kt][1] = sBh[n + ac + 4 + 8 * kt];
                        bl[nt][kt][0] = sBl[n + ac + 8 * kt];
                        bl[nt][kt][1] = sBl[n + ac + 4 + 8 * kt];
                    }
                }
                lastk = k;
            }
            // mma: 2 k-tiles x 4 n-tiles x 3 chains
            #pragma unroll
            for (int kt = 0; kt < 2; kt++) {
                int a0i = ar * 20 + ac + 8 * kt;
                int a1i = (ar + 8) * 20 + ac + 8 * kt;
                uint32_t ah0 = sAh[w][a0i],     ah1 = sAh[w][a1i];
                uint32_t ah2 = sAh[w][a0i + 4], ah3 = sAh[w][a1i + 4];
                uint32_t al0 = sAl[w][a0i],     al1 = sAl[w][a1i];
                uint32_t al2 = sAl[w][a0i + 4], al3 = sAl[w][a1i + 4];
                #pragma unroll
                for (int nt = 0; nt < 4; nt++) {
                    mma_bf16(c[nt], ah0, ah1, ah2, ah3, bh[nt][kt][0], bh[nt][kt][1]);
                    mma_bf16(c[nt], ah0, ah1, ah2, ah3, bl[nt][kt][0], bl[nt][kt][1]);
                    mma_bf16(c[nt], al0, al1, al2, al3, bh[nt][kt][0], bh[nt][kt][1]);
                }
            }
        }
        // epilogue: 2 rows x 4 nt v2-REDs per lane
        int p0 = base + w * 16 + ar;
        int p1 = p0 + 8;
        float* d0 = out + (size_t)s_out[w * 16 + ar] * 32 + ac * 2;
        float* d1 = out + (size_t)s_out[w * 16 + ar + 8] * 32 + ac * 2;
        #pragma unroll
        for (int nt = 0; nt < 4; nt++) {
            if (p0 < U) red_add_v2(d0 + nt * 8, c[nt][0], c[nt][1]);
            if (p1 < U) red_add_v2(d1 + nt * 8, c[nt][2], c[nt][3]);
        }
    }
}

// ------------------------------------ launch --------------------------------
extern "C" void kernel_launch(void* const* d_in, const int* in_sizes, int n_in,
                              void* d_out, int out_size) {
    const float* feat   = (const float*)d_in[0];
    const float* weight = (const float*)d_in[1];
    const float* bias   = (const float*)d_in[2];
    const int* pin      = (const int*)d_in[3];
    const int* pout     = (const int*)d_in[4];
    const int* counts   = (const int*)d_in[5];
    const int* uin      = (const int*)d_in[6];
    const int* uout     = (const int*)d_in[7];
    const int* uk       = (const int*)d_in[8];
    float* out          = (float*)d_out;

    int P = in_sizes[3];
    int M = in_sizes[5];
    int U = in_sizes[6];
    int n8 = out_size / 4;

    int gz = (M + 255) / 256;
    int gi = (n8 + 255) / 256;
    prep_kernel<<<gz + gi, 256>>>((const float4*)feat, (const float4*)bias,
                                  (float4*)out, M, n8, gz);
    fill_kernel<<<(P + 255) / 256, 256>>>(pin, pout, P);
    pool_gather_kernel<<<(M * 8 + 255) / 256, 256>>>((const float4*)feat, counts, M);

    int ntiles = (U + 63) / 64;
    int grid = ntiles < 1024 ? ntiles : 1024;
    up_mma_kernel<<<grid, 128>>>(weight, uin, uout, uk, out, U, ntiles);
}

// round 5
// speedup vs baseline: 1.3453x; 1.3453x over previous
#include <cuda_runtime.h>
#include <cstdint>

// ---------------------------------------------------------------------------
// Round 5:
//   up kernel fully barrier-free: warp-private 16-pair tiles, operands
//   pre-split to bf16 hi/lo in fragment-ready global layouts, B fragments
//   register-cached per k-run, 24 MMA + 8 RED per tile, no SMEM.
// ---------------------------------------------------------------------------

__device__ uint4 g_ah[1000000 * 4];   // pooled hi-split: [m][ac] -> pairs ac+4t
__device__ uint4 g_al[1000000 * 4];   // pooled lo-split
__device__ uint2 g_bh[27 * 256];      // -W hi-split fragments
__device__ uint2 g_bl[27 * 256];      // -W lo-split fragments
__device__ int   g_cursor[1000000];
__device__ int   g_csr[32000000];     // 32-slot buckets per pooled row

static __device__ __forceinline__ void red_add_v2(float* dst, float a, float b) {
    asm volatile("red.global.add.v2.f32 [%0], {%1,%2};"
                 :: "l"(dst), "f"(a), "f"(b) : "memory");
}
static __device__ __forceinline__ uint32_t bf2(float hi, float lo) {
    uint32_t r;
    asm("cvt.rn.bf16x2.f32 %0, %1, %2;" : "=r"(r) : "f"(hi), "f"(lo));
    return r;
}
// v0 -> low half, v1 -> high half; h + l reconstructs to ~2^-16 rel
static __device__ __forceinline__ void split2(float v0, float v1,
                                              uint32_t& h, uint32_t& l) {
    h = bf2(v1, v0);
    float f0 = __uint_as_float(h << 16);
    float f1 = __uint_as_float(h & 0xFFFF0000u);
    l = bf2(v1 - f1, v0 - f0);
}
static __device__ __forceinline__ void mma_bf16(float c[4],
        uint32_t a0, uint32_t a1, uint32_t a2, uint32_t a3,
        uint32_t b0, uint32_t b1) {
    asm volatile(
        "mma.sync.aligned.m16n8k16.row.col.f32.bf16.bf16.f32 "
        "{%0,%1,%2,%3}, {%4,%5,%6,%7}, {%8,%9}, {%0,%1,%2,%3};"
        : "+f"(c[0]), "+f"(c[1]), "+f"(c[2]), "+f"(c[3])
        : "r"(a0), "r"(a1), "r"(a2), "r"(a3), "r"(b0), "r"(b1));
}

// ---- launch 1: weight-split + zero cursors + out = feat - bias (fused) -----
__global__ void prep_kernel(const float* __restrict__ weight,
                            const float4* __restrict__ feat4,
                            const float4* __restrict__ bias4,
                            float4* __restrict__ out4,
                            int M, int n8, int gw, int gz) {
    int b = blockIdx.x;
    if (b < gw) {
        int idx = b * 256 + threadIdx.x;        // 27*256 = 6912 fragments
        if (idx < 27 * 256) {
            int ac = idx & 3, kt = (idx >> 2) & 1, n = (idx >> 3) & 31, k = idx >> 8;
            int j1 = ac + 8 * kt, j2 = ac + 4 + 8 * kt;
            const float* wp = weight + (size_t)k * 1024 + n;
            float w10 = -__ldg(wp + (2 * j1) * 32);
            float w11 = -__ldg(wp + (2 * j1 + 1) * 32);
            float w20 = -__ldg(wp + (2 * j2) * 32);
            float w21 = -__ldg(wp + (2 * j2 + 1) * 32);
            uint32_t h1, l1, h2, l2;
            split2(w10, w11, h1, l1);
            split2(w20, w21, h2, l2);
            g_bh[idx] = make_uint2(h1, h2);
            g_bl[idx] = make_uint2(l1, l2);
        }
        return;
    }
    if (b < gw + gz) {
        int i = (b - gw) * 256 + threadIdx.x;
        if (i < M) g_cursor[i] = 0;
        return;
    }
    int t = (b - gw - gz) * 256 + threadIdx.x;
    if (t >= n8) return;
    float4 v = feat4[t];
    float4 bb = __ldg(bias4 + (t & 7));
    out4[t] = make_float4(v.x - bb.x, v.y - bb.y, v.z - bb.z, v.w - bb.w);
}

// ---- launch 2: scatter pool pairs into buckets ------------------------------
__global__ void fill_kernel(const int* __restrict__ pin,
                            const int* __restrict__ pout, int P) {
    int p = blockIdx.x * 256 + threadIdx.x;
    if (p < P) {
        int o = __ldg(pout + p);
        int s = atomicAdd(&g_cursor[o], 1);
        g_csr[(size_t)o * 32 + s] = __ldg(pin + p);
    }
}

// ---- launch 3: pooled avg, written as hi/lo bf16x2 fragment layout ---------
__global__ void pool_gather_kernel(const float4* __restrict__ feat4,
                                   const int* __restrict__ counts, int M) {
    int t = blockIdx.x * 256 + threadIdx.x;
    if (t >= M * 8) return;
    int m = t >> 3, cg = t & 7;
    int cnt = counts[m];
    const int* row = g_csr + (size_t)m * 32;
    float4 acc = make_float4(0.f, 0.f, 0.f, 0.f);
    for (int e = 0; e < cnt; e++) {
        int idx = __ldg(row + e);
        float4 v = __ldg(&feat4[(size_t)idx * 8 + cg]);
        acc.x += v.x; acc.y += v.y; acc.z += v.z; acc.w += v.w;
    }
    float inv = 1.0f / (float)cnt;
    acc.x *= inv; acc.y *= inv; acc.z *= inv; acc.w *= inv;
    uint32_t h0, l0, h1, l1;
    split2(acc.x, acc.y, h0, l0);   // channel pair p0 = 2*cg
    split2(acc.z, acc.w, h1, l1);   // channel pair p1 = 2*cg+1
    uint32_t* ah = (uint32_t*)g_ah;
    uint32_t* al = (uint32_t*)g_al;
    int p0 = 2 * cg, p1 = 2 * cg + 1;
    ah[(size_t)m * 16 + (p0 & 3) * 4 + (p0 >> 2)] = h0;
    ah[(size_t)m * 16 + (p1 & 3) * 4 + (p1 >> 2)] = h1;
    al[(size_t)m * 16 + (p0 & 3) * 4 + (p0 >> 2)] = l0;
    al[(size_t)m * 16 + (p1 & 3) * 4 + (p1 >> 2)] = l1;
}

// ---- launch 4: up pass — barrier-free warp-private tiles --------------------
// Warp-tile = 16 pairs. D[16x32] += A(16x32) x (-W[k])(32x32), split-3 bf16.
__global__ void __launch_bounds__(128, 6)
up_mma_kernel(const int* __restrict__ uin,
              const int* __restrict__ uout,
              const int* __restrict__ uk,
              float* __restrict__ out, int U, int nwt) {
    int lane = threadIdx.x & 31;
    int ar = lane >> 2, ac = lane & 3;
    int wg = blockIdx.x * 4 + (threadIdx.x >> 5);
    int stride = gridDim.x * 4;
    int lastk = -1;
    uint2 bh[4][2], bl[4][2];

    for (int wt = wg; wt < nwt; wt += stride) {
        int base = wt * 16;
        int p = base + lane;
        int inv = 0, outv = 0, kv = -1;
        if (lane < 16 && p < U) {
            kv = __ldg(uk + p);
            inv = __ldg(uin + p);
            outv = __ldg(uout + p);
        }
        int kmx = kv, kmn = (kv < 0) ? 0x7fffffff : kv;
        #pragma unroll
        for (int d = 16; d; d >>= 1) {
            kmx = max(kmx, __shfl_xor_sync(~0u, kmx, d));
            kmn = min(kmn, __shfl_xor_sync(~0u, kmn, d));
        }
        int in0 = __shfl_sync(~0u, inv, ar), in1 = __shfl_sync(~0u, inv, ar + 8);
        int k0  = __shfl_sync(~0u, kv, ar),  k1  = __shfl_sync(~0u, kv, ar + 8);
        int o0  = __shfl_sync(~0u, outv, ar), o1 = __shfl_sync(~0u, outv, ar + 8);

        float c[4][4];
        #pragma unroll
        for (int i = 0; i < 4; i++)
            #pragma unroll
            for (int j = 0; j < 4; j++) c[i][j] = 0.f;

        for (int k = kmn; k <= kmx; k++) {
            if (k != lastk) {   // warp-uniform; <=27 reloads per warp total
                #pragma unroll
                for (int nt = 0; nt < 4; nt++)
                    #pragma unroll
                    for (int kt = 0; kt < 2; kt++) {
                        int bi = k * 256 + (ar + 8 * nt) * 8 + kt * 4 + ac;
                        bh[nt][kt] = __ldg(&g_bh[bi]);
                        bl[nt][kt] = __ldg(&g_bl[bi]);
                    }
                lastk = k;
            }
            uint4 z = make_uint4(0, 0, 0, 0);
            uint4 Ah0 = (k0 == k) ? __ldg(&g_ah[(size_t)in0 * 4 + ac]) : z;
            uint4 Al0 = (k0 == k) ? __ldg(&g_al[(size_t)in0 * 4 + ac]) : z;
            uint4 Ah1 = (k1 == k) ? __ldg(&g_ah[(size_t)in1 * 4 + ac]) : z;
            uint4 Al1 = (k1 == k) ? __ldg(&g_al[(size_t)in1 * 4 + ac]) : z;
            // kt = 0 uses .x/.y (pairs ac, ac+4); kt = 1 uses .z/.w
            #pragma unroll
            for (int nt = 0; nt < 4; nt++) {
                mma_bf16(c[nt], Ah0.x, Ah1.x, Ah0.y, Ah1.y, bh[nt][0].x, bh[nt][0].y);
                mma_bf16(c[nt], Ah0.x, Ah1.x, Ah0.y, Ah1.y, bl[nt][0].x, bl[nt][0].y);
                mma_bf16(c[nt], Al0.x, Al1.x, Al0.y, Al1.y, bh[nt][0].x, bh[nt][0].y);
                mma_bf16(c[nt], Ah0.z, Ah1.z, Ah0.w, Ah1.w, bh[nt][1].x, bh[nt][1].y);
                mma_bf16(c[nt], Ah0.z, Ah1.z, Ah0.w, Ah1.w, bl[nt][1].x, bl[nt][1].y);
                mma_bf16(c[nt], Al0.z, Al1.z, Al0.w, Al1.w, bh[nt][1].x, bh[nt][1].y);
            }
        }
        bool v0 = (base + ar) < U, v1 = (base + ar + 8) < U;
        float* d0 = out + (size_t)o0 * 32 + ac * 2;
        float* d1 = out + (size_t)o1 * 32 + ac * 2;
        #pragma unroll
        for (int nt = 0; nt < 4; nt++) {
            if (v0) red_add_v2(d0 + nt * 8, c[nt][0], c[nt][1]);
            if (v1) red_add_v2(d1 + nt * 8, c[nt][2], c[nt][3]);
        }
    }
}

// ------------------------------------ launch --------------------------------
extern "C" void kernel_launch(void* const* d_in, const int* in_sizes, int n_in,
                              void* d_out, int out_size) {
    const float* feat   = (const float*)d_in[0];
    const float* weight = (const float*)d_in[1];
    const float* bias   = (const float*)d_in[2];
    const int* pin      = (const int*)d_in[3];
    const int* pout     = (const int*)d_in[4];
    const int* counts   = (const int*)d_in[5];
    const int* uin      = (const int*)d_in[6];
    const int* uout     = (const int*)d_in[7];
    const int* uk       = (const int*)d_in[8];
    float* out          = (float*)d_out;

    int P = in_sizes[3];
    int M = in_sizes[5];
    int U = in_sizes[6];
    int n8 = out_size / 4;

    int gw = 27;                       // 27*256 = 6912 weight fragments
    int gz = (M + 255) / 256;
    int gi = (n8 + 255) / 256;
    prep_kernel<<<gw + gz + gi, 256>>>(weight, (const float4*)feat,
                                       (const float4*)bias, (float4*)out,
                                       M, n8, gw, gz);
    fill_kernel<<<(P + 255) / 256, 256>>>(pin, pout, P);
    pool_gather_kernel<<<(M * 8 + 255) / 256, 256>>>((const float4*)feat, counts, M);

    int nwt = (U + 15) / 16;           // warp-tiles
    int grid = (nwt + 3) / 4;
    if (grid > 1776) grid = 1776;
    up_mma_kernel<<<grid, 128>>>(uin, uout, uk, out, U, nwt);
}